// round 10
// baseline (speedup 1.0000x reference)
#include <cuda_runtime.h>
#include <math.h>

#define SMEM_ROWS 1024     // 12 KB head-row buffer (block 0 only); freeze at ~290 rows
#define NTHREADS  256
#define NBLOCKS   592      // 4 blocks/SM * 148 SMs -> single co-resident wave

// ---------------------------------------------------------------------------
// Role-split fused kernel (one launch, no cross-block communication):
//  * ALL blocks replay the short serial recurrence (deterministic, ~290 iters)
//    to learn the frozen state. Blocks 1..591 use a REGISTER-ONLY replay
//    (pure 8-cyc/iter FMA chain), then immediately fill the constant region.
//  * Block 0 additionally stores the trajectory rows to SMEM and writes the
//    head + geometric transition rows (small; hidden under the big fill).
// The 48 MB constant fill is L2-write-bandwidth bound (~3.5 TB/s, proven
// invariant across store shapes and TMA) — everything else hides under it.
//
// Recurrence (single rounding per value, same order in both variants):
//   u = 1-g+beff*S ; nI = I*u ; nS = fma(-beff*I,S,S) ; nR = fma(g,I,R)
// S monotone non-increasing => bitwise-unchanged across a 32-iter chunk with
// 0<u<1 means frozen forever; tail is exactly geometric then constant.
// ---------------------------------------------------------------------------
__global__ void __launch_bounds__(NTHREADS)
sir_fused_kernel(const float* __restrict__ x,
                 const float* __restrict__ bw,
                 const float* __restrict__ gw,
                 int steps, int total_elems,
                 float* __restrict__ out)
{
    __shared__ __align__(16) float s_rows[SMEM_ROWS * 3];   // used by block 0 only
    __shared__ int    s_nrows, s_r, s_cut;
    __shared__ float  s_S, s_Irec, s_A, s_Rinf;
    __shared__ double s_c;

    const int tid = threadIdx.x;
    const bool is_b0 = (blockIdx.x == 0);

    // ---------------- Prologue (thread 0 of every block) -------------------
    if (tid == 0) {
        float S = x[0], I = x[1], R = x[2];
        const float pop  = __fadd_rn(__fadd_rn(x[0], x[1]), x[2]);
        const float g    = gw[0];
        const float beff = (pop == 1.0f) ? bw[0] : __fdiv_rn(bw[0], pop);
        const float omg  = __fsub_rn(1.0f, g);

        int i = 1;
        bool frozen = false;
        const int cap = (steps < SMEM_ROWS) ? steps : SMEM_ROWS;

        if (is_b0) {
            // ---- Storing variant (block 0): rows into SMEM ----
            s_rows[0] = S; s_rows[1] = I; s_rows[2] = R;
            for (int h = 0; h < 3 && i < steps; ++h, ++i) {
                float u  = __fmaf_rn(beff, S, omg);
                float v  = __fmul_rn(beff, I);
                float nI = __fmul_rn(I, u);
                float nS = __fmaf_rn(-v, S, S);
                float nR = __fmaf_rn(g, I, R);
                S = nS; I = nI; R = nR;
                s_rows[3*i] = S; s_rows[3*i+1] = I; s_rows[3*i+2] = R;
            }
            for (; i + 32 <= cap; i += 32) {
                const float S0 = S;
                float* w = s_rows + 3 * i;
                #pragma unroll
                for (int k = 0; k < 32; ++k) {
                    float u  = __fmaf_rn(beff, S, omg);
                    float v  = __fmul_rn(beff, I);
                    float nI = __fmul_rn(I, u);
                    float nS = __fmaf_rn(-v, S, S);
                    float nR = __fmaf_rn(g, I, R);
                    S = nS; I = nI; R = nR;
                    w[0] = S; w[1] = I; w[2] = R;
                    w += 3;
                }
                if (S == S0) {
                    float u = __fmaf_rn(beff, S, omg);
                    if (u < 1.0f && u > 0.0f) { i += 32; frozen = true; break; }
                }
            }
        } else {
            // ---- Register-only variant (blocks 1..): pure FMA chain ----
            for (int h = 0; h < 3 && i < steps; ++h, ++i) {
                float u  = __fmaf_rn(beff, S, omg);
                float v  = __fmul_rn(beff, I);
                float nI = __fmul_rn(I, u);
                float nS = __fmaf_rn(-v, S, S);
                float nR = __fmaf_rn(g, I, R);
                S = nS; I = nI; R = nR;
            }
            for (; i + 32 <= cap; i += 32) {
                const float S0 = S;
                #pragma unroll
                for (int k = 0; k < 32; ++k) {
                    float u  = __fmaf_rn(beff, S, omg);
                    float v  = __fmul_rn(beff, I);
                    float nI = __fmul_rn(I, u);
                    float nS = __fmaf_rn(-v, S, S);
                    float nR = __fmaf_rn(g, I, R);
                    S = nS; I = nI; R = nR;
                }
                if (S == S0) {
                    float u = __fmaf_rn(beff, S, omg);
                    if (u < 1.0f && u > 0.0f) { i += 32; frozen = true; break; }
                }
            }
        }

        if (frozen) {
            const int r_row = i - 1;
            const float  u  = __fmaf_rn(beff, S, omg);
            const double ud = (double)u;
            const double c  = log2(ud);                    // < 0
            const double Ad = (double)g * (double)I / (1.0 - ud);
            const double Rinf = (double)R + Ad;

            double mx = fmax((double)I, Ad);
            if (mx < 1e-300) mx = 1e-300;
            double t_d = (160.0 + log2(mx)) / (-c);        // u^t below any fp32 effect
            long long cut_ll = r_row + (long long)t_d + 8;
            long long cut4   = ((cut_ll + 3) / 4) * 4;     // multiple of 4 rows
            if (cut4 < (long long)i) cut4 = i;
            int cut = (cut4 > (long long)steps) ? steps : (int)cut4;

            s_nrows = i; s_r = r_row; s_cut = cut;
            s_S = S; s_Irec = I; s_A = (float)Ad; s_Rinf = (float)Rinf; s_c = c;
        } else {
            // Fallback: block 0 finishes serially to gmem; others no-op the fill.
            s_nrows = i; s_r = steps - 1; s_cut = steps;
            if (is_b0) {
                for (; i < steps; ++i) {
                    float u  = __fmaf_rn(beff, S, omg);
                    float v  = __fmul_rn(beff, I);
                    float nI = __fmul_rn(I, u);
                    float nS = __fmaf_rn(-v, S, S);
                    float nR = __fmaf_rn(g, I, R);
                    S = nS; I = nI; R = nR;
                    out[3*i] = S; out[3*i+1] = I; out[3*i+2] = R;
                }
            }
            s_S = S; s_Irec = I; s_A = 0.0f; s_Rinf = R; s_c = 0.0;
        }
    }

    __syncthreads();

    const int   nrows = s_nrows;       // multiple of 4 when frozen
    const int   cut   = s_cut;
    const float S     = s_S;
    const float Rinf  = s_Rinf;

    if (is_b0) {
        // ---- Block 0: head rows + transition rows (tiny; hidden under fill) ----
        const int   r    = s_r;
        const float Irec = s_Irec;
        const float A    = s_A;
        const double c   = s_c;

        // (a) Head rows [0, nrows): smem -> gmem, coalesced float4.
        {
            const int nelem  = 3 * nrows;
            const int count4 = nelem / 4;
            const float4* srcp = reinterpret_cast<const float4*>(s_rows);
            float4*       dstp = reinterpret_cast<float4*>(out);
            for (int idx = tid; idx < count4; idx += NTHREADS)
                dstp[idx] = srcp[idx];
            for (int e = count4 * 4 + tid; e < nelem; e += NTHREADS)
                out[e] = s_rows[e];
        }

        // (b) Transition rows [nrows, cut): geometric closed form.
        {
            const int eBeg = 3 * nrows;
            const int eEnd = 3 * cut;
            for (int e = eBeg + tid; e < eEnd; e += NTHREADS) {
                const int k    = e / 3;
                const int comp = e - 3 * k;
                const float p  = exp2f((float)((double)(k - r) * c));
                out[e] = (comp == 0) ? S
                       : (comp == 1) ? __fmul_rn(Irec, p)
                                     : __fmaf_rn(-A, p, Rinf);
            }
        }

        // (c) Scalar remainder (total_elems % 4 != 0 — not hit for steps = 4M).
        if (tid == 0) {
            const int e0 = (total_elems / 4) * 4;
            for (int e = e0; e < total_elems; ++e) {
                const int k    = e / 3;
                const int comp = e - 3 * k;
                if (k >= cut)
                    out[e] = (comp == 0) ? S : ((comp == 1) ? 0.0f : Rinf);
                else if (k >= nrows) {
                    const float p = exp2f((float)((double)(k - r) * c));
                    out[e] = (comp == 0) ? S
                           : (comp == 1) ? __fmul_rn(Irec, p)
                                         : __fmaf_rn(-A, p, Rinf);
                } else
                    out[e] = s_rows[e];
            }
        }
    } else {
        // ---- Blocks 1..: constant region [cut, steps) = (S, 0, Rinf) ----
        // 3*cut % 12 == 0 -> start4 is a float4 index; fill stride
        // fsize = 591*256 == 0 (mod 3) -> each thread's phase is CONSTANT:
        // the inner loop is just STG.128 + index add + compare.
        const int n4     = total_elems / 4;
        const int start4 = (3 * cut) / 4;
        const int fsize  = (NBLOCKS - 1) * NTHREADS;

        int j = start4 + (blockIdx.x - 1) * NTHREADS + tid;
        const int ph = j % 3;
        const float4 P = (ph == 0) ? make_float4(S,    0.0f, Rinf, S)
                       : (ph == 1) ? make_float4(0.0f, Rinf, S,    0.0f)
                                   : make_float4(Rinf, S,    0.0f, Rinf);

        float4* out4 = reinterpret_cast<float4*>(out);
        for (; j < n4; j += fsize)
            out4[j] = P;
    }
}

extern "C" void kernel_launch(void* const* d_in, const int* in_sizes, int n_in,
                              void* d_out, int out_size)
{
    const float* x  = (const float*)d_in[0];
    const float* bw = (const float*)d_in[1];
    const float* gw = (const float*)d_in[2];
    float* out = (float*)d_out;

    const int steps = out_size / 3;

    sir_fused_kernel<<<NBLOCKS, NTHREADS>>>(x, bw, gw, steps, out_size, out);
}